// round 1
// baseline (speedup 1.0000x reference)
#include <cuda_runtime.h>
#include <cstdint>

// Problem shape (fixed by reference)
constexpr int VOCAB = 128000;
constexpr int EMBED = 256;
constexpr int BATCH = 64;
constexpr int BLOCK = 2048;
constexpr int NTOK  = BATCH * BLOCK;       // 131072 tokens
constexpr int VEC_PER_ROW = EMBED / 4;     // 64 float4 per row

__device__ __forceinline__ void stcs_f4(float4* p, float4 v) {
    // streaming store: evict-first in L2 so output writes don't evict the
    // embedding table (which nearly fits in 126MB L2)
    asm volatile("st.global.cs.v4.f32 [%0], {%1,%2,%3,%4};"
                 :: "l"(p), "f"(v.x), "f"(v.y), "f"(v.z), "f"(v.w) : "memory");
}

__global__ __launch_bounds__(256)
void embed_softmax_kernel(const int* __restrict__ idx,
                          const float* __restrict__ emb,
                          float* __restrict__ out) {
    const int warp = (blockIdx.x * blockDim.x + threadIdx.x) >> 5;
    const int lane = threadIdx.x & 31;
    if (warp >= NTOK) return;

    const int row = __ldg(idx + warp);
    const float4* __restrict__ src =
        reinterpret_cast<const float4*>(emb + (size_t)row * EMBED);

    // 64 float4 per row, 32 lanes -> 2 vec loads per lane (fully coalesced 1KB)
    float4 a = __ldg(src + lane);
    float4 b = __ldg(src + 32 + lane);

    float e0 = __expf(a.x), e1 = __expf(a.y), e2 = __expf(a.z), e3 = __expf(a.w);
    float e4 = __expf(b.x), e5 = __expf(b.y), e6 = __expf(b.z), e7 = __expf(b.w);

    float s = ((e0 + e1) + (e2 + e3)) + ((e4 + e5) + (e6 + e7));
    #pragma unroll
    for (int o = 16; o > 0; o >>= 1)
        s += __shfl_xor_sync(0xFFFFFFFFu, s, o);

    const float inv = __frcp_rn(s);

    float4* __restrict__ logit_dst =
        reinterpret_cast<float4*>(out) + (size_t)warp * VEC_PER_ROW;
    float4* __restrict__ prob_dst =
        logit_dst + (size_t)NTOK * VEC_PER_ROW;

    // logits: straight copy of gathered row
    stcs_f4(logit_dst + lane, a);
    stcs_f4(logit_dst + 32 + lane, b);

    // probs: exp * inv_sum
    stcs_f4(prob_dst + lane,      make_float4(e0 * inv, e1 * inv, e2 * inv, e3 * inv));
    stcs_f4(prob_dst + 32 + lane, make_float4(e4 * inv, e5 * inv, e6 * inv, e7 * inv));
}

extern "C" void kernel_launch(void* const* d_in, const int* in_sizes, int n_in,
                              void* d_out, int out_size) {
    // metadata order: idx (int32, 131072), embedding (f32, 32768000).
    // Defensive: identify by size in case of reordering.
    const int* idx;
    const float* emb;
    if (in_sizes[0] == NTOK) {
        idx = (const int*)d_in[0];
        emb = (const float*)d_in[1];
    } else {
        idx = (const int*)d_in[1];
        emb = (const float*)d_in[0];
    }
    float* out = (float*)d_out;

    // one warp per token: 131072 warps -> 256-thread blocks, 8 warps each
    const int threads = 256;
    const int blocks = (NTOK * 32) / threads;  // 16384
    embed_softmax_kernel<<<blocks, threads>>>(idx, emb, out);
}

// round 2
// speedup vs baseline: 1.0106x; 1.0106x over previous
#include <cuda_runtime.h>
#include <cstdint>

// Problem shape (fixed by reference)
constexpr int VOCAB = 128000;
constexpr int EMBED = 256;
constexpr int BATCH = 64;
constexpr int BLOCK = 2048;
constexpr int NTOK  = BATCH * BLOCK;       // 131072 tokens
constexpr int VEC_PER_ROW = EMBED / 4;     // 64 float4 per row
constexpr int TOK_PER_WARP = 4;

__device__ __forceinline__ void stcs_f4(float4* p, float4 v) {
    // streaming store: evict-first in L2 so the 256MB of output writes don't
    // evict the embedding table (128MB, nearly fits in 126MB L2)
    asm volatile("st.global.cs.v4.f32 [%0], {%1,%2,%3,%4};"
                 :: "l"(p), "f"(v.x), "f"(v.y), "f"(v.z), "f"(v.w) : "memory");
}

__global__ __launch_bounds__(256)
void embed_softmax_kernel(const int* __restrict__ idx,
                          const float* __restrict__ emb,
                          float* __restrict__ out) {
    const int warp = (blockIdx.x * blockDim.x + threadIdx.x) >> 5;
    const int lane = threadIdx.x & 31;
    // warp handles tokens [warp*4, warp*4+4)
    if (warp * TOK_PER_WARP >= NTOK) return;

    // one vectorized idx load covers all 4 tokens (amortizes first-hop latency)
    const int4 rows = __ldg(reinterpret_cast<const int4*>(idx) + warp);
    const int r[TOK_PER_WARP] = {rows.x, rows.y, rows.z, rows.w};

    // issue ALL 8 row loads up-front: 4KB in flight per warp (MLP=8)
    float4 a[TOK_PER_WARP], b[TOK_PER_WARP];
    #pragma unroll
    for (int t = 0; t < TOK_PER_WARP; t++) {
        const float4* __restrict__ src =
            reinterpret_cast<const float4*>(emb + (size_t)r[t] * EMBED);
        a[t] = __ldg(src + lane);
        b[t] = __ldg(src + 32 + lane);
    }

    float4* __restrict__ out4 = reinterpret_cast<float4*>(out);
    const size_t prob_off = (size_t)NTOK * VEC_PER_ROW;

    #pragma unroll
    for (int t = 0; t < TOK_PER_WARP; t++) {
        const size_t tok = (size_t)warp * TOK_PER_WARP + t;
        float4* __restrict__ logit_dst = out4 + tok * VEC_PER_ROW;

        // store logits now so a/b registers can be overwritten by exp
        stcs_f4(logit_dst + lane,      a[t]);
        stcs_f4(logit_dst + 32 + lane, b[t]);

        // exp in place
        a[t].x = __expf(a[t].x); a[t].y = __expf(a[t].y);
        a[t].z = __expf(a[t].z); a[t].w = __expf(a[t].w);
        b[t].x = __expf(b[t].x); b[t].y = __expf(b[t].y);
        b[t].z = __expf(b[t].z); b[t].w = __expf(b[t].w);

        float s = ((a[t].x + a[t].y) + (a[t].z + a[t].w))
                + ((b[t].x + b[t].y) + (b[t].z + b[t].w));
        #pragma unroll
        for (int o = 16; o > 0; o >>= 1)
            s += __shfl_xor_sync(0xFFFFFFFFu, s, o);
        const float inv = __frcp_rn(s);

        float4* __restrict__ prob_dst = logit_dst + prob_off;
        stcs_f4(prob_dst + lane,
                make_float4(a[t].x * inv, a[t].y * inv, a[t].z * inv, a[t].w * inv));
        stcs_f4(prob_dst + 32 + lane,
                make_float4(b[t].x * inv, b[t].y * inv, b[t].z * inv, b[t].w * inv));
    }
}

extern "C" void kernel_launch(void* const* d_in, const int* in_sizes, int n_in,
                              void* d_out, int out_size) {
    const int* idx;
    const float* emb;
    if (in_sizes[0] == NTOK) {
        idx = (const int*)d_in[0];
        emb = (const float*)d_in[1];
    } else {
        idx = (const int*)d_in[1];
        emb = (const float*)d_in[0];
    }
    float* out = (float*)d_out;

    // 4 tokens per warp: 32768 warps -> 256-thread blocks (8 warps) -> 4096 blocks
    const int threads = 256;
    const int warps = NTOK / TOK_PER_WARP;
    const int blocks = (warps * 32) / threads;
    embed_softmax_kernel<<<blocks, threads>>>(idx, emb, out);
}

// round 4
// speedup vs baseline: 1.0155x; 1.0048x over previous
#include <cuda_runtime.h>
#include <cstdint>

// Problem shape (fixed by reference)
constexpr int EMBED = 256;
constexpr int BATCH = 64;
constexpr int BLOCK = 2048;
constexpr int NTOK  = BATCH * BLOCK;       // 131072 tokens
constexpr int VEC_PER_ROW = EMBED / 4;     // 64 float4 per row

__device__ __forceinline__ void stcs_f4(float4* p, float4 v) {
    // streaming store: evict-first in L2 so the 256MB of output writes don't
    // evict the embedding table (128MB, nearly fits in 126MB L2)
    asm volatile("st.global.cs.v4.f32 [%0], {%1,%2,%3,%4};"
                 :: "l"(p), "f"(v.x), "f"(v.y), "f"(v.z), "f"(v.w) : "memory");
}

struct f8 { float v[8]; };

__device__ __forceinline__ f8 ldg_persist_f8(const float* p) {
    // 256-bit read-only load with L2 evict_last (sm_103a ptxas only accepts
    // the evict hint on .v8.b32): pins the embedding table in L2 so gather
    // misses approach the capacity floor across graph replays.
    f8 r;
    asm volatile("ld.global.nc.L2::evict_last.v8.f32 "
                 "{%0,%1,%2,%3,%4,%5,%6,%7}, [%8];"
                 : "=f"(r.v[0]), "=f"(r.v[1]), "=f"(r.v[2]), "=f"(r.v[3]),
                   "=f"(r.v[4]), "=f"(r.v[5]), "=f"(r.v[6]), "=f"(r.v[7])
                 : "l"(p));
    return r;
}

__global__ __launch_bounds__(256)
void embed_softmax_kernel(const int* __restrict__ idx,
                          const float* __restrict__ emb,
                          float* __restrict__ out) {
    const int warp = (blockIdx.x * blockDim.x + threadIdx.x) >> 5;
    const int lane = threadIdx.x & 31;
    if (warp >= NTOK) return;

    const int row = __ldg(idx + warp);

    // one 256-bit load per lane covers the whole 1KB row across the warp
    f8 a = ldg_persist_f8(emb + (size_t)row * EMBED + lane * 8);

    float4* __restrict__ logit_dst =
        reinterpret_cast<float4*>(out) + (size_t)warp * VEC_PER_ROW;
    float4* __restrict__ prob_dst =
        logit_dst + (size_t)NTOK * VEC_PER_ROW;

    // store logits immediately (straight copy of gathered row).
    // lane's 8 floats are contiguous: two adjacent float4 at vec index lane*2.
    stcs_f4(logit_dst + lane * 2,
            make_float4(a.v[0], a.v[1], a.v[2], a.v[3]));
    stcs_f4(logit_dst + lane * 2 + 1,
            make_float4(a.v[4], a.v[5], a.v[6], a.v[7]));

    float e[8];
    #pragma unroll
    for (int i = 0; i < 8; i++) e[i] = __expf(a.v[i]);

    float s = ((e[0] + e[1]) + (e[2] + e[3])) + ((e[4] + e[5]) + (e[6] + e[7]));
    #pragma unroll
    for (int o = 16; o > 0; o >>= 1)
        s += __shfl_xor_sync(0xFFFFFFFFu, s, o);

    const float inv = __frcp_rn(s);

    stcs_f4(prob_dst + lane * 2,
            make_float4(e[0] * inv, e[1] * inv, e[2] * inv, e[3] * inv));
    stcs_f4(prob_dst + lane * 2 + 1,
            make_float4(e[4] * inv, e[5] * inv, e[6] * inv, e[7] * inv));
}

extern "C" void kernel_launch(void* const* d_in, const int* in_sizes, int n_in,
                              void* d_out, int out_size) {
    const int* idx;
    const float* emb;
    if (in_sizes[0] == NTOK) {
        idx = (const int*)d_in[0];
        emb = (const float*)d_in[1];
    } else {
        idx = (const int*)d_in[1];
        emb = (const float*)d_in[0];
    }
    float* out = (float*)d_out;

    // one warp per token: 131072 warps -> 256-thread blocks, 8 warps each
    const int threads = 256;
    const int blocks = (NTOK * 32) / threads;  // 16384
    embed_softmax_kernel<<<blocks, threads>>>(idx, emb, out);
}